// round 12
// baseline (speedup 1.0000x reference)
#include <cuda_runtime.h>
#include <cuda_bf16.h>
#include <cstdint>

// Problem constants
#define BB 16
#define NN 16384
#define PP 4096
#define FF 128
#define TT 1024
#define PPT (NN / TT)   // 16 points per thread

// FPS indices scratch (device global — no allocation allowed)
__device__ int g_fps_idx[BB * PP];

// SMEM layout (dynamic):
//   float2 sxy[NN]            : 131072 B
//   float  sz [NN]            :  65536 B
//   unsigned long long best[2]:     16 B
#define SMEM_XY_OFF   0
#define SMEM_Z_OFF    (NN * 8)
#define SMEM_BEST_OFF (NN * 12)
#define SMEM_BYTES    (NN * 12 + 16)

// LLVM DAGCombiner contraction of the canonical left-assoc reduce
// ((0+dx^2)+dy^2)+dz^2, with the zero-init folded away:
//   fadd(fmul(dx,dx), fmul(dy,dy)) -> fma(dx,dx, dy*dy)   (fuse operand 0)
//   fadd(<fma>, fmul(dz,dz))       -> fma(dz,dz, <fma>)   (fuse the mul)
// => d = fma(dz,dz, fma(dx,dx, dy*dy))
__device__ __forceinline__ float dist_ref(float dx, float dy, float dz) {
    return __fmaf_rn(dz, dz, __fmaf_rn(dx, dx, __fmul_rn(dy, dy)));
}

__global__ void __launch_bounds__(TT, 1)
fps_kernel(const float* __restrict__ pos)
{
    extern __shared__ char smem[];
    float2* sxy = reinterpret_cast<float2*>(smem + SMEM_XY_OFF);
    float*  sz  = reinterpret_cast<float*>(smem + SMEM_Z_OFF);
    unsigned long long* sbest =
        reinterpret_cast<unsigned long long*>(smem + SMEM_BEST_OFF);

    const int b   = blockIdx.x;
    const int tid = threadIdx.x;
    const float* px = pos + (size_t)b * 3 * NN;  // x rows, then y, then z

    // Stage coords into SMEM (coalesced global reads)
    #pragma unroll
    for (int j = 0; j < PPT; ++j) {
        int n = j * TT + tid;
        sxy[n] = make_float2(px[n], px[NN + n]);
        sz[n]  = px[2 * NN + n];
    }
    if (tid < 2) sbest[tid] = 0ULL;
    if (tid == 0) g_fps_idx[b * PP + 0] = 0;
    __syncthreads();

    // Query = point 0 for the initial distance pass
    float qx = sxy[0].x, qy = sxy[0].y, qz = sz[0];

    float md[PPT];
    #pragma unroll
    for (int j = 0; j < PPT; ++j) {
        int n = j * TT + tid;
        float2 xy = sxy[n];
        float dx = __fadd_rn(xy.x, -qx);   // x + (-q) == x - q exactly
        float dy = __fadd_rn(xy.y, -qy);
        float dz = __fadd_rn(sz[n], -qz);
        md[j] = dist_ref(dx, dy, dz);
    }

    for (int it = 1; it < PP; ++it) {
        // ---- local argmax over this thread's 16 values ----
        float best_v = -1.0f;
        int   best_n = 0;
        if (it == 1) {
            #pragma unroll
            for (int j = 0; j < PPT; ++j) {
                int n = j * TT + tid;
                if (md[j] > best_v) { best_v = md[j]; best_n = n; }
            }
        } else {
            // fused: update md vs current query while scanning for max
            #pragma unroll
            for (int j = 0; j < PPT; ++j) {
                int n = j * TT + tid;
                float2 xy = sxy[n];
                float dx = __fadd_rn(xy.x, -qx);
                float dy = __fadd_rn(xy.y, -qy);
                float dz = __fadd_rn(sz[n], -qz);
                float d  = dist_ref(dx, dy, dz);
                float m = fminf(md[j], d);
                md[j] = m;
                if (m > best_v) { best_v = m; best_n = n; }
            }
        }

        // ---- warp reduce (max value; ties -> lower index) ----
        #pragma unroll
        for (int off = 16; off > 0; off >>= 1) {
            float ov = __shfl_down_sync(0xFFFFFFFFu, best_v, off);
            int   on = __shfl_down_sync(0xFFFFFFFFu, best_n, off);
            if (ov > best_v || (ov == best_v && on < best_n)) {
                best_v = ov; best_n = on;
            }
        }

        // ---- cross-warp argmax via packed u64 atomicMax ----
        // key = (float_bits(v) << 32) | (0xFFFFFFFF - n)
        // v >= 0 so float bits are order-preserving; inverted index makes
        // the smaller index win ties. Deterministic regardless of atomic order.
        const int slot = it & 1;
        if ((tid & 31) == 0) {
            unsigned long long key =
                ((unsigned long long)__float_as_uint(best_v) << 32) |
                (unsigned long long)(0xFFFFFFFFu - (unsigned)best_n);
            atomicMax(&sbest[slot], key);
        }
        __syncthreads();

        unsigned long long k = sbest[slot];
        int sel = (int)(0xFFFFFFFFu - (unsigned)(k & 0xFFFFFFFFull));

        // broadcast the newly selected point's coords (uniform LDS)
        float2 sxy_sel = sxy[sel];
        qx = sxy_sel.x; qy = sxy_sel.y; qz = sz[sel];

        if (tid == 0) {
            g_fps_idx[b * PP + it] = sel;
            sbest[slot ^ 1] = 0ULL;  // reset the other slot for next iter
        }
        __syncthreads();  // orders the reset before next iter's atomics
    }
}

// Gather: out = [x_out (B,F,P), pos_out (B,3,P)] flattened, float32.
__global__ void gather_kernel(const float* __restrict__ x,
                              const float* __restrict__ pos,
                              float* __restrict__ out)
{
    const int total1 = BB * FF * PP;          // 8388608
    const int total2 = BB * 3 * PP;           // 196608
    int t = blockIdx.x * blockDim.x + threadIdx.x;
    if (t < total1) {
        int p = t & (PP - 1);
        int f = (t >> 12) & (FF - 1);         // PP = 4096 = 2^12
        int b = t >> 19;                      // / (FF*PP) = / 2^19
        int i = g_fps_idx[b * PP + p];
        out[t] = x[(size_t)b * FF * NN + (size_t)f * NN + i];
    } else if (t < total1 + total2) {
        int t2 = t - total1;
        int p = t2 & (PP - 1);
        int c = (t2 >> 12) % 3;
        int b = t2 / (3 * PP);
        int i = g_fps_idx[b * PP + p];
        out[t] = pos[(size_t)b * 3 * NN + (size_t)c * NN + i];
    }
}

extern "C" void kernel_launch(void* const* d_in, const int* in_sizes, int n_in,
                              void* d_out, int out_size)
{
    // Identify inputs by element count (robust to metadata ordering):
    //   pos: 16*3*16384  = 786432 floats
    //   x  : 16*128*16384 = 33554432 floats
    const float* pos = (const float*)d_in[0];
    const float* x   = (const float*)(n_in > 1 ? d_in[1] : d_in[0]);
    for (int i = 0; i < n_in; ++i) {
        if (in_sizes[i] == BB * 3 * NN)  pos = (const float*)d_in[i];
        if (in_sizes[i] == BB * FF * NN) x   = (const float*)d_in[i];
    }

    // >48KB dynamic SMEM needs the opt-in attribute (idempotent, capture-safe)
    cudaFuncSetAttribute(fps_kernel,
                         cudaFuncAttributeMaxDynamicSharedMemorySize,
                         SMEM_BYTES);

    fps_kernel<<<BB, TT, SMEM_BYTES>>>(pos);

    const int total = BB * FF * PP + BB * 3 * PP;
    gather_kernel<<<(total + 255) / 256, 256>>>(x, pos, (float*)d_out);
    (void)out_size;
}

// round 14
// speedup vs baseline: 1.6807x; 1.6807x over previous
#include <cuda_runtime.h>
#include <cuda_bf16.h>
#include <cstdint>

// Problem constants
#define BB 16
#define NN 16384
#define PP 4096
#define FF 128
#define TT 1024
#define PPT (NN / TT)     // 16 points per thread (= one spatial group)
#define NCELL 512         // 8x8x8 Morton cells

// FPS indices scratch (device global — no allocation allowed)
__device__ int g_fps_idx[BB * PP];

// ---- dynamic SMEM layout (bytes) ----
// float2 sxy[NN]     @0       : 131072
// float  sz [NN]     @131072  :  65536
// u16    sorig[NN]   @196608  :  32768
// u32    hist[512]   @229376  :   2048
// u32    slotA[4]    @231424  :     16   (phase-A value max, float bits)
// u32    slotB[4]    @231440  :     16   (phase-B (orig<<16)|phys, min)
// u32    sbb[6]      @231456  :     24   (batch bbox reduce, encoded)
#define OFF_XY    0
#define OFF_Z     131072
#define OFF_ORIG  196608
#define OFF_HIST  229376
#define OFF_SA    231424
#define OFF_SB    231440
#define OFF_BB    231456
#define SMEM_BYTES 231488   // <= 232448 (227 KB opt-in limit)

// Reference distance chain (validated rel_err==0 in round 12):
//   d = fma(dz,dz, fma(dx,dx, dy*dy))
__device__ __forceinline__ float dist_ref(float dx, float dy, float dz) {
    return __fmaf_rn(dz, dz, __fmaf_rn(dx, dx, __fmul_rn(dy, dy)));
}

// order-preserving float<->u32 map (for min/max atomics on any-sign floats)
__device__ __forceinline__ unsigned fenc(float f) {
    unsigned u = __float_as_uint(f);
    return (u & 0x80000000u) ? ~u : (u | 0x80000000u);
}
__device__ __forceinline__ float fdec(unsigned e) {
    unsigned u = (e & 0x80000000u) ? (e ^ 0x80000000u) : ~e;
    return __uint_as_float(u);
}

// expand 3 bits for Morton interleave
__device__ __forceinline__ unsigned exp3(unsigned v) {
    return (v & 1u) | ((v & 2u) << 2) | ((v & 4u) << 4);
}

__global__ void __launch_bounds__(TT, 1)
fps_kernel(const float* __restrict__ pos)
{
    extern __shared__ char smem[];
    float2*         sxy   = reinterpret_cast<float2*>(smem + OFF_XY);
    float*          sz    = reinterpret_cast<float*>(smem + OFF_Z);
    unsigned short* sorig = reinterpret_cast<unsigned short*>(smem + OFF_ORIG);
    unsigned*       hist  = reinterpret_cast<unsigned*>(smem + OFF_HIST);
    unsigned*       slotA = reinterpret_cast<unsigned*>(smem + OFF_SA);
    unsigned*       slotB = reinterpret_cast<unsigned*>(smem + OFF_SB);
    unsigned*       sbb   = reinterpret_cast<unsigned*>(smem + OFF_BB);

    const int b    = blockIdx.x;
    const int tid  = threadIdx.x;
    const int lane = tid & 31;
    const float* px = pos + (size_t)b * 3 * NN;  // x rows, then y, then z

    // ---- init smem control state ----
    for (int c = tid; c < NCELL; c += TT) hist[c] = 0;
    if (tid < 4) { slotA[tid] = 0u; slotB[tid] = 0xFFFFFFFFu; }
    if (tid < 3) { sbb[tid] = 0xFFFFFFFFu; sbb[3 + tid] = 0u; }
    if (tid == 0) g_fps_idx[b * PP + 0] = 0;

    // ---- pass 1a: batch bbox ----
    float mnx = 1e30f, mxx = -1e30f, mny = 1e30f, mxy = -1e30f,
          mnz = 1e30f, mxz = -1e30f;
    #pragma unroll
    for (int j = 0; j < PPT; ++j) {
        int n = j * TT + tid;
        float x = px[n], y = px[NN + n], z = px[2 * NN + n];
        mnx = fminf(mnx, x); mxx = fmaxf(mxx, x);
        mny = fminf(mny, y); mxy = fmaxf(mxy, y);
        mnz = fminf(mnz, z); mxz = fmaxf(mxz, z);
    }
    __syncthreads();  // init visible before atomics
    atomicMin(&sbb[0], fenc(mnx)); atomicMax(&sbb[3], fenc(mxx));
    atomicMin(&sbb[1], fenc(mny)); atomicMax(&sbb[4], fenc(mxy));
    atomicMin(&sbb[2], fenc(mnz)); atomicMax(&sbb[5], fenc(mxz));
    __syncthreads();

    const float ox = fdec(sbb[0]), oy = fdec(sbb[1]), oz = fdec(sbb[2]);
    const float sxq = 8.0f / fmaxf(fdec(sbb[3]) - ox, 1e-30f);
    const float syq = 8.0f / fmaxf(fdec(sbb[4]) - oy, 1e-30f);
    const float szq = 8.0f / fmaxf(fdec(sbb[5]) - oz, 1e-30f);

    // ---- pass 1b: Morton cell + histogram ----
    unsigned cellreg[PPT];
    #pragma unroll
    for (int j = 0; j < PPT; ++j) {
        int n = j * TT + tid;
        float x = px[n], y = px[NN + n], z = px[2 * NN + n];
        int cx = min(7, max(0, (int)((x - ox) * sxq)));
        int cy = min(7, max(0, (int)((y - oy) * syq)));
        int cz = min(7, max(0, (int)((z - oz) * szq)));
        unsigned cell = exp3(cx) | (exp3(cy) << 1) | (exp3(cz) << 2);
        cellreg[j] = cell;
        atomicAdd(&hist[cell], 1u);
    }
    __syncthreads();

    // ---- exclusive scan over 512 cells (warp 0) ----
    if (tid < 32) {
        unsigned loc[16], tot = 0;
        #pragma unroll
        for (int k = 0; k < 16; ++k) { loc[k] = hist[tid * 16 + k]; tot += loc[k]; }
        unsigned incl = tot;
        #pragma unroll
        for (int off = 1; off < 32; off <<= 1) {
            unsigned v = __shfl_up_sync(0xFFFFFFFFu, incl, off);
            if (lane >= off) incl += v;
        }
        unsigned run = incl - tot;   // exclusive base
        #pragma unroll
        for (int k = 0; k < 16; ++k) { hist[tid * 16 + k] = run; run += loc[k]; }
    }
    __syncthreads();

    // ---- pass 1c: scatter into swizzled sorted layout ----
    // logical sorted pos spos -> group g=spos>>4, j0=spos&15
    // phys = g*16 + ((j0 + gam + 5*(gam>>4)) & 15), gam = g & 31
    // (swizzle is conflict-free for the strided read pattern below)
    #pragma unroll
    for (int j = 0; j < PPT; ++j) {
        int n = j * TT + tid;
        float x = px[n], y = px[NN + n], z = px[2 * NN + n];
        unsigned spos = atomicAdd(&hist[cellreg[j]], 1u);
        unsigned g = spos >> 4, j0 = spos & 15u, gam = g & 31u;
        unsigned ph = (g << 4) + ((j0 + gam + 5u * (gam >> 4)) & 15u);
        sxy[ph] = make_float2(x, y);
        sz[ph]  = z;
        sorig[ph] = (unsigned short)n;
    }
    __syncthreads();

    // ---- init: md vs original point 0; per-thread (group) bbox ----
    const unsigned gam = (unsigned)(tid & 31);
    const unsigned c0  = gam + 5u * (gam >> 4);   // swizzle constant

    float qx = px[0], qy = px[NN], qz = px[2 * NN];
    float md[PPT];
    float bx0 = 1e30f, bx1 = -1e30f, by0 = 1e30f, by1 = -1e30f,
          bz0 = 1e30f, bz1 = -1e30f;
    float bv = 0.0f;
    #pragma unroll
    for (int j = 0; j < PPT; ++j) {
        int ph = (tid << 4) + (int)((j + c0) & 15u);
        float2 xy = sxy[ph];
        float  zz = sz[ph];
        bx0 = fminf(bx0, xy.x); bx1 = fmaxf(bx1, xy.x);
        by0 = fminf(by0, xy.y); by1 = fmaxf(by1, xy.y);
        bz0 = fminf(bz0, zz);   bz1 = fmaxf(bz1, zz);
        float dx = __fadd_rn(xy.x, -qx);
        float dy = __fadd_rn(xy.y, -qy);
        float dz = __fadd_rn(zz,   -qz);
        float d = dist_ref(dx, dy, dz);
        md[j] = d;
        bv = fmaxf(bv, d);
    }

    // ---- main FPS loop ----
    for (int it = 1; it < PP; ++it) {
        if (it > 1) {
            // exact skip test: lower bound of dist(q, bbox)^2 vs max md.
            // 1.002 margin absorbs ~1e-6 relative rounding in both the bound
            // and the per-point distance chain -> skipped mins are no-ops.
            float gx = fmaxf(fmaxf(__fadd_rn(bx0, -qx), __fadd_rn(qx, -bx1)), 0.0f);
            float gy = fmaxf(fmaxf(__fadd_rn(by0, -qy), __fadd_rn(qy, -by1)), 0.0f);
            float gz = fmaxf(fmaxf(__fadd_rn(bz0, -qz), __fadd_rn(qz, -bz1)), 0.0f);
            float dbox = dist_ref(gx, gy, gz);
            if (!(dbox >= __fmul_rn(bv, 1.002f))) {
                float nbv = 0.0f;
                #pragma unroll
                for (int j = 0; j < PPT; ++j) {
                    int ph = (tid << 4) + (int)((j + c0) & 15u);
                    float2 xy = sxy[ph];
                    float  zz = sz[ph];
                    float dx = __fadd_rn(xy.x, -qx);
                    float dy = __fadd_rn(xy.y, -qy);
                    float dz = __fadd_rn(zz,   -qz);
                    float d  = dist_ref(dx, dy, dz);
                    float m  = fminf(md[j], d);
                    md[j] = m;
                    nbv = fmaxf(nbv, m);
                }
                bv = nbv;
            }
        }

        // ---- phase A: global max VALUE only ----
        const int slot = it & 3;
        float w = bv;
        #pragma unroll
        for (int off = 16; off > 0; off >>= 1)
            w = fmaxf(w, __shfl_xor_sync(0xFFFFFFFFu, w, off));
        if (lane == 0)
            atomicMax(&slotA[slot], __float_as_uint(w));  // md>=0: bits order ok
        __syncthreads();
        const float vmax = __uint_as_float(slotA[slot]);

        // ---- phase B: resolve index (lowest ORIGINAL index wins ties) ----
        if (bv == vmax) {
            #pragma unroll
            for (int j = 0; j < PPT; ++j) {
                if (md[j] == vmax) {
                    int ph = (tid << 4) + (int)((j + c0) & 15u);
                    unsigned o = (unsigned)sorig[ph];
                    atomicMin(&slotB[slot], (o << 16) | (unsigned)ph);
                }
            }
        }
        __syncthreads();

        const unsigned k = slotB[slot];
        const int physw = (int)(k & 0xFFFFu);
        const int origw = (int)(k >> 16);

        float2 q2 = sxy[physw];
        qx = q2.x; qy = q2.y; qz = sz[physw];

        if (tid == 0) {
            g_fps_idx[b * PP + it] = origw;
            slotA[(it + 2) & 3] = 0u;            // reused 2 iters later —
            slotB[(it + 2) & 3] = 0xFFFFFFFFu;   // ordered by the 2 barriers
        }
    }
}

// Gather: out = [x_out (B,F,P), pos_out (B,3,P)] flattened, float32.
__global__ void gather_kernel(const float* __restrict__ x,
                              const float* __restrict__ pos,
                              float* __restrict__ out)
{
    const int total1 = BB * FF * PP;          // 8388608
    const int total2 = BB * 3 * PP;           // 196608
    int t = blockIdx.x * blockDim.x + threadIdx.x;
    if (t < total1) {
        int p = t & (PP - 1);
        int f = (t >> 12) & (FF - 1);         // PP = 4096 = 2^12
        int b = t >> 19;                      // / (FF*PP) = / 2^19
        int i = g_fps_idx[b * PP + p];
        out[t] = x[(size_t)b * FF * NN + (size_t)f * NN + i];
    } else if (t < total1 + total2) {
        int t2 = t - total1;
        int p = t2 & (PP - 1);
        int c = (t2 >> 12) % 3;
        int b = t2 / (3 * PP);
        int i = g_fps_idx[b * PP + p];
        out[t] = pos[(size_t)b * 3 * NN + (size_t)c * NN + i];
    }
}

extern "C" void kernel_launch(void* const* d_in, const int* in_sizes, int n_in,
                              void* d_out, int out_size)
{
    const float* pos = (const float*)d_in[0];
    const float* x   = (const float*)(n_in > 1 ? d_in[1] : d_in[0]);
    for (int i = 0; i < n_in; ++i) {
        if (in_sizes[i] == BB * 3 * NN)  pos = (const float*)d_in[i];
        if (in_sizes[i] == BB * FF * NN) x   = (const float*)d_in[i];
    }

    cudaFuncSetAttribute(fps_kernel,
                         cudaFuncAttributeMaxDynamicSharedMemorySize,
                         SMEM_BYTES);

    fps_kernel<<<BB, TT, SMEM_BYTES>>>(pos);

    const int total = BB * FF * PP + BB * 3 * PP;
    gather_kernel<<<(total + 255) / 256, 256>>>(x, pos, (float*)d_out);
    (void)out_size;
}